// round 3
// baseline (speedup 1.0000x reference)
#include <cuda_runtime.h>

#define NROWS 1000000
#define H     128
#define K     64
#define TEMP  30.0f
#define MTILE 256          // rows per block in k3
#define RPT   8            // rows per thread
#define ZSTRF 128          // zn_s row stride in floats (swizzle handles banks)

typedef unsigned long long u64;

// Packed fp32x2 FMA (Blackwell): d = a*b + c elementwise on 2 floats.
__device__ __forceinline__ u64 ffma2(u64 a, u64 b, u64 c) {
    u64 d;
    asm("fma.rn.f32x2 %0, %1, %2, %3;" : "=l"(d) : "l"(a), "l"(b), "l"(c));
    return d;
}
__device__ __forceinline__ float hsum2(u64 v) {
    float x, y;
    asm("mov.b64 {%0, %1}, %2;" : "=f"(x), "=f"(y) : "l"(v));
    return x + y;
}

// Scratch accumulators (no device mallocs allowed).
__device__ float g_sums[K * H];
__device__ float g_cnts[K];

// ---------------------------------------------------------------------------
// k0: zero the global accumulators (graph replays must be deterministic)
// ---------------------------------------------------------------------------
__global__ void k_zero() {
    int i = blockIdx.x * blockDim.x + threadIdx.x;
    if (i < K * H) g_sums[i] = 0.0f;
    if (i < K)     g_cnts[i] = 0.0f;
}

// ---------------------------------------------------------------------------
// k1: row-wise L2 normalize z -> zn, accumulate per-community sums/counts.
// ---------------------------------------------------------------------------
__global__ void __launch_bounds__(256)
k_norm_acc(const float* __restrict__ z, const int* __restrict__ comm,
           float* __restrict__ zn) {
    __shared__ float s_sum[K * H];
    __shared__ float s_cnt[K];

    int tid = threadIdx.x;
    for (int i = tid; i < K * H; i += blockDim.x) s_sum[i] = 0.0f;
    if (tid < K) s_cnt[tid] = 0.0f;
    __syncthreads();

    int lane   = tid & 31;
    int warp   = tid >> 5;
    int nwarps = blockDim.x >> 5;

    for (long row = (long)blockIdx.x * nwarps + warp; row < NROWS;
         row += (long)gridDim.x * nwarps) {
        const float* zr = z + row * (long)H;
        float v0 = zr[lane];
        float v1 = zr[lane + 32];
        float v2 = zr[lane + 64];
        float v3 = zr[lane + 96];
        float ss = v0 * v0 + v1 * v1 + v2 * v2 + v3 * v3;
        #pragma unroll
        for (int o = 16; o; o >>= 1) ss += __shfl_xor_sync(0xffffffffu, ss, o);
        float inv = rsqrtf(ss);
        v0 *= inv; v1 *= inv; v2 *= inv; v3 *= inv;

        float* znr = zn + row * (long)H;
        znr[lane]      = v0;
        znr[lane + 32] = v1;
        znr[lane + 64] = v2;
        znr[lane + 96] = v3;

        int c = comm[row];
        float* sb = s_sum + c * H;
        atomicAdd(sb + lane,      v0);
        atomicAdd(sb + lane + 32, v1);
        atomicAdd(sb + lane + 64, v2);
        atomicAdd(sb + lane + 96, v3);
        if (lane == 0) atomicAdd(&s_cnt[c], 1.0f);
    }
    __syncthreads();

    for (int i = tid; i < K * H; i += blockDim.x)
        atomicAdd(&g_sums[i], s_sum[i]);
    if (tid < K) atomicAdd(&g_cnts[tid], s_cnt[tid]);
}

// ---------------------------------------------------------------------------
// k2: mu = sums / counts
// ---------------------------------------------------------------------------
__global__ void k_mu(float* __restrict__ mu) {
    int i = blockIdx.x * blockDim.x + threadIdx.x;
    if (i < K * H) {
        float c = g_cnts[i / H];
        mu[i] = g_sums[i] / fmaxf(c, 1.0f);
    }
}

// ---------------------------------------------------------------------------
// k3: register-tiled GEMM dist = zn @ mu^T + fused softmax -> r
//   Block = 256 threads = 32 (m) x 8 (kk). Thread owns rows 8m..8m+7 and
//   k-cols [8kk, 8kk+8). Packed f32x2 accumulators (even-h, odd-h partials).
//   Arithmetic intensity: per hc-step a thread loads 16x16B from smem and
//   issues 128 FFMA2 (4 lane-FMA per smem float).
//   Swizzles (16B granularity):
//     zn_s slot = hc ^ ((row>>3)&7)  -> 4 distinct m per warp, conflict-free
//     mu_s slot = hc ^ (k>>3)        -> 8 distinct kk per warp, conflict-free
// ---------------------------------------------------------------------------
extern __shared__ float k3_smem[];

__global__ void __launch_bounds__(256, 1)
k_dist_softmax(const float* __restrict__ zn, const float* __restrict__ mu,
               float* __restrict__ r, float* __restrict__ dist) {
    float* zn_s = k3_smem;                 // MTILE * ZSTRF floats (swizzled)
    float* mu_s = k3_smem + MTILE * ZSTRF; // K * H floats (swizzled)

    int tid  = threadIdx.x;
    long base = (long)blockIdx.x * MTILE;

    // Stage mu (8192 floats), swizzle slot = hc ^ (k>>3).
    {
        const float4* mug  = (const float4*)mu;
        float4*       mus4 = (float4*)mu_s;
        #pragma unroll
        for (int i = 0; i < (K * H / 4) / 256; i++) {   // 8 iters
            int v  = i * 256 + tid;
            int k  = v >> 5;
            int hc = v & 31;
            mus4[k * 32 + (hc ^ (k >> 3))] = mug[v];
        }
    }
    // Stage zn tile (MTILE x H), swizzle slot = hc ^ ((row>>3)&7).
    {
        const float4* zng  = (const float4*)zn;
        float4*       zns4 = (float4*)zn_s;
        #pragma unroll
        for (int i = 0; i < (MTILE * 32) / 256; i++) {  // 32 iters
            int v   = i * 256 + tid;
            int row = v >> 5;
            int hc  = v & 31;
            float4 val = make_float4(0.f, 0.f, 0.f, 0.f);
            if (base + row < NROWS) val = zng[(base + row) * 32 + hc];
            zns4[row * 32 + (hc ^ ((row >> 3) & 7))] = val;
        }
    }
    __syncthreads();

    int m  = tid >> 3;   // 0..31
    int kk = tid & 7;    // 0..7
    int r0 = RPT * m;    // local row base
    int msw = m & 7;     // zn swizzle key (row>>3 == m for these rows)

    u64 acc[RPT][8];
    #pragma unroll
    for (int i = 0; i < RPT; i++)
        #pragma unroll
        for (int q = 0; q < 8; q++) acc[i][q] = 0ull;

    const float* znb = zn_s + r0 * ZSTRF;
    const float* mub = mu_s + (8 * kk) * H;

    #pragma unroll 2
    for (int hc = 0; hc < 32; hc++) {
        int zs = (hc ^ msw) * 4;
        int ms = (hc ^ kk) * 4;

        ulonglong2 m2[8];
        #pragma unroll
        for (int q = 0; q < 8; q++)
            m2[q] = *(const ulonglong2*)(mub + q * H + ms);

        #pragma unroll
        for (int i = 0; i < RPT; i++) {
            ulonglong2 z2 = *(const ulonglong2*)(znb + i * ZSTRF + zs);
            #pragma unroll
            for (int q = 0; q < 8; q++) {
                acc[i][q] = ffma2(z2.x, m2[q].x, acc[i][q]);
                acc[i][q] = ffma2(z2.y, m2[q].y, acc[i][q]);
            }
        }
    }

    // Per-row epilogue: combine partials, softmax over 8 kk-lanes, store.
    #pragma unroll
    for (int i = 0; i < RPT; i++) {
        long row = base + r0 + i;
        bool valid = row < NROWS;

        float v[8];
        #pragma unroll
        for (int q = 0; q < 8; q++) v[q] = hsum2(acc[i][q]);

        float mx = v[0];
        #pragma unroll
        for (int q = 1; q < 8; q++) mx = fmaxf(mx, v[q]);
        #pragma unroll
        for (int o = 4; o; o >>= 1)
            mx = fmaxf(mx, __shfl_xor_sync(0xffffffffu, mx, o));

        float e[8], sum = 0.f;
        #pragma unroll
        for (int q = 0; q < 8; q++) {
            e[q] = __expf(TEMP * (v[q] - mx));
            sum += e[q];
        }
        #pragma unroll
        for (int o = 4; o; o >>= 1)
            sum += __shfl_xor_sync(0xffffffffu, sum, o);
        float is = 1.0f / sum;

        if (valid) {
            float* dr = dist + row * (long)K + 8 * kk;
            float* rr = r    + row * (long)K + 8 * kk;
            *(float4*)(dr)     = make_float4(v[0], v[1], v[2], v[3]);
            *(float4*)(dr + 4) = make_float4(v[4], v[5], v[6], v[7]);
            *(float4*)(rr)     = make_float4(e[0] * is, e[1] * is, e[2] * is, e[3] * is);
            *(float4*)(rr + 4) = make_float4(e[4] * is, e[5] * is, e[6] * is, e[7] * is);
        }
    }
}

// ---------------------------------------------------------------------------
// kernel_launch: out layout = zn [N*H] | mu [K*H] | r [N*K] | dist [N*K]
// ---------------------------------------------------------------------------
extern "C" void kernel_launch(void* const* d_in, const int* in_sizes, int n_in,
                              void* d_out, int out_size) {
    const float* z    = (const float*)d_in[0];
    const int*   comm = (const int*)d_in[1];

    float* out  = (float*)d_out;
    float* zn   = out;
    float* mu   = zn + (long)NROWS * H;
    float* rr   = mu + (long)K * H;
    float* dist = rr + (long)NROWS * K;

    const int k3_smem_bytes = (MTILE * ZSTRF + K * H) * sizeof(float); // 163840
    static bool attr_set = false;
    if (!attr_set) {
        cudaFuncSetAttribute(k_dist_softmax,
                             cudaFuncAttributeMaxDynamicSharedMemorySize,
                             k3_smem_bytes);
        attr_set = true;
    }

    k_zero<<<(K * H + 255) / 256, 256>>>();
    k_norm_acc<<<592, 256>>>(z, comm, zn);
    k_mu<<<(K * H + 255) / 256, 256>>>(mu);

    int nblk = (NROWS + MTILE - 1) / MTILE;  // 3907
    k_dist_softmax<<<nblk, 256, k3_smem_bytes>>>(zn, mu, rr, dist);
}

// round 6
// speedup vs baseline: 1.4927x; 1.4927x over previous
#include <cuda_runtime.h>
#include <cstdint>

#define NROWS 1000000
#define H     128
#define K     64
#define TEMP  30.0f
#define TILE_M 128
#define TTOT  ((NROWS + TILE_M - 1) / TILE_M)   // 7813
#define SSTR  132    // smem row stride in floats (132 % 32 == 4 -> conflict-free)

// ---------------- scratch (no device mallocs allowed) ----------------
__device__ float g_sums[K * H];
__device__ float g_cnts[K];

// ---------------- PTX helpers (baseline PTX only) ----------------
__device__ __forceinline__ uint32_t smem_u32(const void* p) {
    uint32_t a;
    asm("{ .reg .u64 t; cvta.to.shared.u64 t, %1; cvt.u32.u64 %0, t; }"
        : "=r"(a) : "l"(p));
    return a;
}
#define CP_ASYNC16(dst, src) \
    asm volatile("cp.async.cg.shared.global [%0], [%1], 16;" :: "r"(dst), "l"(src))
#define CP_COMMIT()  asm volatile("cp.async.commit_group;")
#define CP_WAIT0()   asm volatile("cp.async.wait_group 0;" ::: "memory")

__device__ __forceinline__ uint32_t to_tf32(float f) {
    uint32_t u;
    asm("cvt.rna.tf32.f32 %0, %1;" : "=r"(u) : "f"(f));
    return u;
}
// m16n8k8 tf32 MMA, fp32 accum
__device__ __forceinline__ void mma_tf32(float* c, const uint32_t* a, const uint32_t* b) {
    asm volatile(
        "mma.sync.aligned.m16n8k8.row.col.f32.tf32.tf32.f32 "
        "{%0,%1,%2,%3}, {%4,%5,%6,%7}, {%8,%9}, {%0,%1,%2,%3};"
        : "+f"(c[0]), "+f"(c[1]), "+f"(c[2]), "+f"(c[3])
        : "r"(a[0]), "r"(a[1]), "r"(a[2]), "r"(a[3]), "r"(b[0]), "r"(b[1]));
}

// ---------------------------------------------------------------------------
__global__ void k_zero() {
    int i = blockIdx.x * blockDim.x + threadIdx.x;
    if (i < K * H) g_sums[i] = 0.0f;
    if (i < K)     g_cnts[i] = 0.0f;
}

// ---------------------------------------------------------------------------
// k1: row-wise L2 normalize z -> zn, accumulate per-community sums/counts.
// ---------------------------------------------------------------------------
__global__ void __launch_bounds__(256)
k_norm_acc(const float* __restrict__ z, const int* __restrict__ comm,
           float* __restrict__ zn) {
    __shared__ float s_sum[K * H];
    __shared__ float s_cnt[K];

    int tid = threadIdx.x;
    for (int i = tid; i < K * H; i += blockDim.x) s_sum[i] = 0.0f;
    if (tid < K) s_cnt[tid] = 0.0f;
    __syncthreads();

    int lane   = tid & 31;
    int warp   = tid >> 5;
    int nwarps = blockDim.x >> 5;

    for (long row = (long)blockIdx.x * nwarps + warp; row < NROWS;
         row += (long)gridDim.x * nwarps) {
        const float* zr = z + row * (long)H;
        float v0 = zr[lane];
        float v1 = zr[lane + 32];
        float v2 = zr[lane + 64];
        float v3 = zr[lane + 96];
        float ss = v0 * v0 + v1 * v1 + v2 * v2 + v3 * v3;
        #pragma unroll
        for (int o = 16; o; o >>= 1) ss += __shfl_xor_sync(0xffffffffu, ss, o);
        float inv = rsqrtf(ss);
        v0 *= inv; v1 *= inv; v2 *= inv; v3 *= inv;

        float* znr = zn + row * (long)H;
        znr[lane]      = v0;
        znr[lane + 32] = v1;
        znr[lane + 64] = v2;
        znr[lane + 96] = v3;

        int c = comm[row];
        float* sb = s_sum + c * H;
        atomicAdd(sb + lane,      v0);
        atomicAdd(sb + lane + 32, v1);
        atomicAdd(sb + lane + 64, v2);
        atomicAdd(sb + lane + 96, v3);
        if (lane == 0) atomicAdd(&s_cnt[c], 1.0f);
    }
    __syncthreads();

    for (int i = tid; i < K * H; i += blockDim.x)
        atomicAdd(&g_sums[i], s_sum[i]);
    if (tid < K) atomicAdd(&g_cnts[tid], s_cnt[tid]);
}

// ---------------------------------------------------------------------------
__global__ void k_mu(float* __restrict__ mu) {
    int i = blockIdx.x * blockDim.x + threadIdx.x;
    if (i < K * H) {
        float c = g_cnts[i / H];
        mu[i] = g_sums[i] / fmaxf(c, 1.0f);
    }
}

// ---------------------------------------------------------------------------
// k3: dist = zn @ mu^T via tf32 mma.sync.m16n8k8, fused softmax -> r.
//   fp32 tiles in smem, natural row-major, stride SSTR floats.
//   k-permutation trick: logical k=q <-> physical col 8s+2q, k=q+4 <-> 8s+2q+1,
//   so every fragment load is a contiguous float2 (no ldmatrix needed) and
//   A/B use consistent k mapping. 128 threads = 4 warps; warp owns 32 rows
//   (2 m16 tiles) x all 64 cols (8 n8 tiles). fp32 accumulate in registers.
// ---------------------------------------------------------------------------
extern __shared__ float k3s[];

__global__ void __launch_bounds__(128, 2)
k_dist_mma(const float* __restrict__ zn, const float* __restrict__ mu,
           float* __restrict__ r, float* __restrict__ dist) {
    float* As = k3s;                     // TILE_M rows x SSTR
    float* Bs = k3s + TILE_M * SSTR;     // K rows x SSTR

    int tid  = threadIdx.x;
    long base = (long)blockIdx.x * TILE_M;

    // Stage A (zn tile) via cp.async: 128 rows x 32 float4
    {
        uint32_t a_b = smem_u32(As);
        #pragma unroll
        for (int i = 0; i < 32; i++) {
            int idx = i * 128 + tid;
            int row = idx >> 5, ch = idx & 31;
            long gr = base + row; if (gr >= NROWS) gr = NROWS - 1;
            CP_ASYNC16(a_b + (row * SSTR + ch * 4) * 4,
                       zn + gr * (long)H + ch * 4);
        }
    }
    // Stage B (mu): 64 rows x 32 float4
    {
        uint32_t b_b = smem_u32(Bs);
        #pragma unroll
        for (int i = 0; i < 16; i++) {
            int idx = i * 128 + tid;
            int row = idx >> 5, ch = idx & 31;
            CP_ASYNC16(b_b + (row * SSTR + ch * 4) * 4,
                       mu + row * H + ch * 4);
        }
    }
    CP_COMMIT();
    CP_WAIT0();
    __syncthreads();

    int lane = tid & 31, wid = tid >> 5;
    int qr = lane >> 2;        // quad row 0..7
    int qc = lane & 3;         // quad col 0..3

    const float* aBase = As + (wid * 32 + qr) * SSTR + 2 * qc;
    const float* bBase = Bs + qr * SSTR + 2 * qc;

    float c[2][8][4];
    #pragma unroll
    for (int mt = 0; mt < 2; mt++)
        #pragma unroll
        for (int nt = 0; nt < 8; nt++)
            #pragma unroll
            for (int q = 0; q < 4; q++) c[mt][nt][q] = 0.0f;

    #pragma unroll
    for (int s = 0; s < 16; s++) {
        int co = s * 8;

        uint32_t ua[2][4];
        #pragma unroll
        for (int mt = 0; mt < 2; mt++) {
            float2 lo = *(const float2*)(aBase + mt * 16 * SSTR + co);
            float2 hi = *(const float2*)(aBase + (mt * 16 + 8) * SSTR + co);
            ua[mt][0] = to_tf32(lo.x);  // row r,   k=q
            ua[mt][1] = to_tf32(hi.x);  // row r+8, k=q
            ua[mt][2] = to_tf32(lo.y);  // row r,   k=q+4
            ua[mt][3] = to_tf32(hi.y);  // row r+8, k=q+4
        }

        #pragma unroll
        for (int nt = 0; nt < 8; nt++) {
            float2 bv = *(const float2*)(bBase + nt * 8 * SSTR + co);
            uint32_t ub[2] = { to_tf32(bv.x), to_tf32(bv.y) };
            mma_tf32(c[0][nt], ua[0], ub);
            mma_tf32(c[1][nt], ua[1], ub);
        }
    }

    // Epilogue: thread's quad owns rows (wid*32 + mt*16 + qr) and +8.
    #pragma unroll
    for (int mt = 0; mt < 2; mt++) {
        long ra = base + wid * 32 + mt * 16 + qr;
        long rb = ra + 8;

        float va[16], vb[16];
        #pragma unroll
        for (int nt = 0; nt < 8; nt++) {
            va[2 * nt] = c[mt][nt][0]; va[2 * nt + 1] = c[mt][nt][1];
            vb[2 * nt] = c[mt][nt][2]; vb[2 * nt + 1] = c[mt][nt][3];
        }

        float mxa = va[0], mxb = vb[0];
        #pragma unroll
        for (int i = 1; i < 16; i++) {
            mxa = fmaxf(mxa, va[i]);
            mxb = fmaxf(mxb, vb[i]);
        }
        mxa = fmaxf(mxa, __shfl_xor_sync(0xffffffffu, mxa, 1));
        mxa = fmaxf(mxa, __shfl_xor_sync(0xffffffffu, mxa, 2));
        mxb = fmaxf(mxb, __shfl_xor_sync(0xffffffffu, mxb, 1));
        mxb = fmaxf(mxb, __shfl_xor_sync(0xffffffffu, mxb, 2));

        float ea[16], eb[16], sa = 0.0f, sbv = 0.0f;
        #pragma unroll
        for (int i = 0; i < 16; i++) {
            ea[i] = __expf(TEMP * (va[i] - mxa)); sa  += ea[i];
            eb[i] = __expf(TEMP * (vb[i] - mxb)); sbv += eb[i];
        }
        sa  += __shfl_xor_sync(0xffffffffu, sa, 1);
        sa  += __shfl_xor_sync(0xffffffffu, sa, 2);
        sbv += __shfl_xor_sync(0xffffffffu, sbv, 1);
        sbv += __shfl_xor_sync(0xffffffffu, sbv, 2);
        float isa = 1.0f / sa, isb = 1.0f / sbv;

        int colb = qc * 2;
        if (ra < NROWS) {
            float* dr = dist + ra * (long)K + colb;
            float* rr = r    + ra * (long)K + colb;
            #pragma unroll
            for (int nt = 0; nt < 8; nt++) {
                *(float2*)(dr + nt * 8) = make_float2(va[2 * nt], va[2 * nt + 1]);
                *(float2*)(rr + nt * 8) = make_float2(ea[2 * nt] * isa, ea[2 * nt + 1] * isa);
            }
        }
        if (rb < NROWS) {
            float* dr = dist + rb * (long)K + colb;
            float* rr = r    + rb * (long)K + colb;
            #pragma unroll
            for (int nt = 0; nt < 8; nt++) {
                *(float2*)(dr + nt * 8) = make_float2(vb[2 * nt], vb[2 * nt + 1]);
                *(float2*)(rr + nt * 8) = make_float2(eb[2 * nt] * isb, eb[2 * nt + 1] * isb);
            }
        }
    }
}

// ---------------------------------------------------------------------------
// kernel_launch: out layout = zn [N*H] | mu [K*H] | r [N*K] | dist [N*K]
// ---------------------------------------------------------------------------
extern "C" void kernel_launch(void* const* d_in, const int* in_sizes, int n_in,
                              void* d_out, int out_size) {
    const float* z    = (const float*)d_in[0];
    const int*   comm = (const int*)d_in[1];

    float* out  = (float*)d_out;
    float* zn   = out;
    float* mu   = zn + (long)NROWS * H;
    float* rr   = mu + (long)K * H;
    float* dist = rr + (long)NROWS * K;

    const int k3_smem_bytes = (TILE_M + K) * SSTR * sizeof(float);  // 101376
    static bool attr_set = false;
    if (!attr_set) {
        cudaFuncSetAttribute(k_dist_mma,
                             cudaFuncAttributeMaxDynamicSharedMemorySize,
                             k3_smem_bytes);
        attr_set = true;
    }

    k_zero<<<(K * H + 255) / 256, 256>>>();
    k_norm_acc<<<592, 256>>>(z, comm, zn);
    k_mu<<<(K * H + 255) / 256, 256>>>(mu);
    k_dist_mma<<<TTOT, 128, k3_smem_bytes>>>(zn, mu, rr, dist);
}